// round 1
// baseline (speedup 1.0000x reference)
#include <cuda_runtime.h>
#include <math.h>

#define BQ 4096
#define DD 256
#define NNEG 32768

// scratch (no allocations allowed)
__device__ float g_rowsum[BQ];
__device__ float g_colsum[BQ];
__device__ float g_negsum[BQ];
__device__ float g_diag[BQ];
__device__ int   g_offsets[BQ];

__device__ __forceinline__ float get_inv_tau(const float* log_tau) {
    float t = expf(log_tau[0]);
    t = fminf(fmaxf(t, 1e-4f), 1.0f);
    return 1.0f / t;
}

// ---------------------------------------------------------------- zero
__global__ void k_zero() {
    int i = blockIdx.x * blockDim.x + threadIdx.x;
    if (i < BQ) { g_rowsum[i] = 0.f; g_colsum[i] = 0.f; }
}

// ---------------------------------------------------------------- offsets scan (1 block, 1024 thr)
__global__ void k_scan(const int* __restrict__ counts) {
    __shared__ int s[1024];
    int t = threadIdx.x;
    int c0 = counts[4*t+0], c1 = counts[4*t+1], c2 = counts[4*t+2], c3 = counts[4*t+3];
    int tot = c0 + c1 + c2 + c3;
    s[t] = tot;
    __syncthreads();
    for (int off = 1; off < 1024; off <<= 1) {
        int v = (t >= off) ? s[t - off] : 0;
        __syncthreads();
        s[t] += v;
        __syncthreads();
    }
    int excl = s[t] - tot;
    g_offsets[4*t+0] = excl;
    g_offsets[4*t+1] = excl + c0;
    g_offsets[4*t+2] = excl + c0 + c1;
    g_offsets[4*t+3] = excl + c0 + c1 + c2;
}

// ---------------------------------------------------------------- negatives + diagonal (1 block per query, 128 thr)
__global__ void k_neg(const float* __restrict__ q, const float* __restrict__ p,
                      const float* __restrict__ n, const int* __restrict__ counts,
                      const float* __restrict__ log_tau) {
    int i = blockIdx.x;
    float inv_tau = get_inv_tau(log_tau);
    __shared__ float qs[DD];
    __shared__ float warp_part[4];
    int tid = threadIdx.x;
    // load q row (128 thr x float2 = 256 floats)
    ((float2*)qs)[tid] = ((const float2*)(q + (size_t)i * DD))[tid];
    __syncthreads();
    int w = tid >> 5, lane = tid & 31;
    int cnt = counts[i];
    int off = g_offsets[i];

    float4 b0 = ((const float4*)qs)[lane * 2 + 0];
    float4 b1 = ((const float4*)qs)[lane * 2 + 1];

    float part = 0.f;
    for (int k = w; k < cnt; k += 4) {
        const float* nr = n + (size_t)(off + k) * DD;
        float4 a0 = ((const float4*)nr)[lane * 2 + 0];
        float4 a1 = ((const float4*)nr)[lane * 2 + 1];
        float dot = a0.x*b0.x + a0.y*b0.y + a0.z*b0.z + a0.w*b0.w
                  + a1.x*b1.x + a1.y*b1.y + a1.z*b1.z + a1.w*b1.w;
        #pragma unroll
        for (int m = 16; m > 0; m >>= 1) dot += __shfl_xor_sync(0xFFFFFFFFu, dot, m);
        if (lane == 0) part += __expf(dot * inv_tau);
    }
    if (lane == 0) warp_part[w] = part;

    // diagonal: warp 0 computes dot(q_i, p_i)
    if (w == 0) {
        const float* pr = p + (size_t)i * DD;
        float4 a0 = ((const float4*)pr)[lane * 2 + 0];
        float4 a1 = ((const float4*)pr)[lane * 2 + 1];
        float dot = a0.x*b0.x + a0.y*b0.y + a0.z*b0.z + a0.w*b0.w
                  + a1.x*b1.x + a1.y*b1.y + a1.z*b1.z + a1.w*b1.w;
        #pragma unroll
        for (int m = 16; m > 0; m >>= 1) dot += __shfl_xor_sync(0xFFFFFFFFu, dot, m);
        if (lane == 0) g_diag[i] = dot * inv_tau;
    }
    __syncthreads();
    if (tid == 0)
        g_negsum[i] = warp_part[0] + warp_part[1] + warp_part[2] + warp_part[3];
}

// ---------------------------------------------------------------- GEMM + exp-sum epilogue
// 128x128 tile, BK=16, 256 threads, 8x8 micro-tile per thread.
#define BM 128
#define BN 128
#define BK 16
#define SPAD 4

__global__ __launch_bounds__(256, 2)
void k_gemm(const float* __restrict__ q, const float* __restrict__ p,
            const float* __restrict__ log_tau) {
    __shared__ float As[BK][BM + SPAD];
    __shared__ float Bs[BK][BN + SPAD];

    int m0 = blockIdx.y * BM;
    int n0 = blockIdx.x * BN;
    int tid = threadIdx.x;
    int tx = tid & 15;          // 0..15 -> 8 cols each
    int ty = tid >> 4;          // 0..15 -> 8 rows each
    float inv_tau = get_inv_tau(log_tau);

    float acc[8][8];
    #pragma unroll
    for (int r = 0; r < 8; r++)
        #pragma unroll
        for (int c = 0; c < 8; c++) acc[r][c] = 0.f;

    for (int kt = 0; kt < DD / BK; kt++) {
        int k0 = kt * BK;
        // load 128x16 tiles of A and B (512 float4 total each, 2 per thread)
        #pragma unroll
        for (int l = 0; l < 2; l++) {
            int id = tid + 256 * l;
            int r = id >> 2;
            int c = (id & 3) << 2;
            float4 av = *(const float4*)(q + (size_t)(m0 + r) * DD + k0 + c);
            As[c+0][r] = av.x; As[c+1][r] = av.y; As[c+2][r] = av.z; As[c+3][r] = av.w;
            float4 bv = *(const float4*)(p + (size_t)(n0 + r) * DD + k0 + c);
            Bs[c+0][r] = bv.x; Bs[c+1][r] = bv.y; Bs[c+2][r] = bv.z; Bs[c+3][r] = bv.w;
        }
        __syncthreads();

        #pragma unroll
        for (int kk = 0; kk < BK; kk++) {
            float4 a0 = *(const float4*)&As[kk][ty * 8];
            float4 a1 = *(const float4*)&As[kk][ty * 8 + 4];
            float4 bb0 = *(const float4*)&Bs[kk][tx * 8];
            float4 bb1 = *(const float4*)&Bs[kk][tx * 8 + 4];
            float ar[8] = {a0.x,a0.y,a0.z,a0.w,a1.x,a1.y,a1.z,a1.w};
            float br[8] = {bb0.x,bb0.y,bb0.z,bb0.w,bb1.x,bb1.y,bb1.z,bb1.w};
            #pragma unroll
            for (int r = 0; r < 8; r++)
                #pragma unroll
                for (int c = 0; c < 8; c++)
                    acc[r][c] = fmaf(ar[r], br[c], acc[r][c]);
        }
        __syncthreads();
    }

    // ---- epilogue: e = exp(acc/tau); reduce rows (shuffle over tx) + cols (smem) ----
    #pragma unroll
    for (int r = 0; r < 8; r++)
        #pragma unroll
        for (int c = 0; c < 8; c++)
            acc[r][c] = __expf(acc[r][c] * inv_tau);

    // rows: lane = (ty&1)*16 + tx, so xor over bits 0..3 reduces across tx
    #pragma unroll
    for (int r = 0; r < 8; r++) {
        float v = 0.f;
        #pragma unroll
        for (int c = 0; c < 8; c++) v += acc[r][c];
        v += __shfl_xor_sync(0xFFFFFFFFu, v, 1);
        v += __shfl_xor_sync(0xFFFFFFFFu, v, 2);
        v += __shfl_xor_sync(0xFFFFFFFFu, v, 4);
        v += __shfl_xor_sync(0xFFFFFFFFu, v, 8);
        if (tx == 0) atomicAdd(&g_rowsum[m0 + ty * 8 + r], v);
    }

    // cols: each thread writes its per-ty column partials to smem, then 128 thr reduce over ty
    float (*cb)[BN] = (float(*)[BN])&As[0][0];   // 16*128 floats fits in As
    #pragma unroll
    for (int c = 0; c < 8; c++) {
        float v = 0.f;
        #pragma unroll
        for (int r = 0; r < 8; r++) v += acc[r][c];
        cb[ty][tx * 8 + c] = v;
    }
    __syncthreads();
    if (tid < BN) {
        float v = 0.f;
        #pragma unroll
        for (int t = 0; t < 16; t++) v += cb[t][tid];
        atomicAdd(&g_colsum[n0 + tid], v);
    }
}

// ---------------------------------------------------------------- finalize (1 block)
__global__ void k_final(float* __restrict__ out) {
    __shared__ float red[256];
    int tid = threadIdx.x;
    float a = 0.f;
    for (int i = tid; i < BQ; i += 256) {
        a += 2.f * g_diag[i]
           - logf(g_rowsum[i] + g_negsum[i])
           - logf(g_colsum[i]);
    }
    red[tid] = a;
    __syncthreads();
    for (int s = 128; s > 0; s >>= 1) {
        if (tid < s) red[tid] += red[tid + s];
        __syncthreads();
    }
    if (tid == 0) out[0] = -red[0] / (2.f * (float)BQ);
}

// ---------------------------------------------------------------- launch
extern "C" void kernel_launch(void* const* d_in, const int* in_sizes, int n_in,
                              void* d_out, int out_size) {
    const float* q       = (const float*)d_in[0];
    const float* p       = (const float*)d_in[1];
    const float* n       = (const float*)d_in[2];
    const int*   counts  = (const int*)d_in[3];
    const float* log_tau = (const float*)d_in[4];
    float* out = (float*)d_out;

    k_zero<<<(BQ + 255) / 256, 256>>>();
    k_scan<<<1, 1024>>>(counts);
    k_neg<<<BQ, 128>>>(q, p, n, counts, log_tau);
    dim3 grid(BQ / BN, BQ / BM);
    k_gemm<<<grid, 256>>>(q, p, log_tau);
    k_final<<<1, 256>>>(out);
}

// round 3
// speedup vs baseline: 2.0990x; 2.0990x over previous
#include <cuda_runtime.h>
#include <math.h>
#include <stdint.h>

#define BQ 4096
#define DD 256
#define NNEG 32768

// ---------------- arch-feature guard: tcgen05 only exists on sm_103a/sm_100a ----------------
#if (defined(__CUDA_ARCH_FEAT_SM103_ALL) || defined(__CUDA_ARCH_FEAT_SM100_ALL) || \
     (defined(__CUDA_ARCH_SPECIFIC__) && (__CUDA_ARCH_SPECIFIC__ == 1030 || __CUDA_ARCH_SPECIFIC__ == 1000)) || \
     (defined(__CUDA_ARCH_FAMILY_SPECIFIC__) && (__CUDA_ARCH_FAMILY_SPECIFIC__ == 1030 || __CUDA_ARCH_FAMILY_SPECIFIC__ == 1000)))
#define HAS_TCGEN05 1
#else
#define HAS_TCGEN05 0
#endif

// ---------------- scratch (no allocations allowed) ----------------
__device__ float g_rowsum[BQ];
__device__ float g_colsum[BQ];
__device__ float g_negsum[BQ];
__device__ float g_diag[BQ];
__device__ int   g_offsets[BQ];

__device__ __forceinline__ float get_inv_tau(const float* log_tau) {
    float t = expf(log_tau[0]);
    t = fminf(fmaxf(t, 1e-4f), 1.0f);
    return 1.0f / t;
}

#if HAS_TCGEN05
// ---------------- PTX helpers (sm_103a only) ----------------
__device__ __forceinline__ uint32_t smem_u32(const void* p) {
    return (uint32_t)__cvta_generic_to_shared(p);
}
__device__ __forceinline__ void mbar_init(uint32_t a, uint32_t cnt) {
    asm volatile("mbarrier.init.shared.b64 [%0], %1;" :: "r"(a), "r"(cnt) : "memory");
}
__device__ __forceinline__ void mbar_wait(uint32_t a, uint32_t phase) {
    uint32_t done;
    do {
        asm volatile("{\n\t.reg .pred p;\n\t"
                     "mbarrier.try_wait.parity.shared::cta.b64 p, [%1], %2, 0x989680;\n\t"
                     "selp.b32 %0, 1, 0, p;\n\t}"
                     : "=r"(done) : "r"(a), "r"(phase) : "memory");
    } while (!done);
}
__device__ __forceinline__ void fence_async_shared() {
    asm volatile("fence.proxy.async.shared::cta;" ::: "memory");
}
__device__ __forceinline__ void tc_alloc(uint32_t smem_dst, uint32_t ncols) {
    asm volatile("tcgen05.alloc.cta_group::1.sync.aligned.shared::cta.b32 [%0], %1;"
                 :: "r"(smem_dst), "r"(ncols) : "memory");
}
__device__ __forceinline__ void tc_relinquish() {
    asm volatile("tcgen05.relinquish_alloc_permit.cta_group::1.sync.aligned;");
}
__device__ __forceinline__ void tc_dealloc(uint32_t tmem, uint32_t ncols) {
    asm volatile("tcgen05.dealloc.cta_group::1.sync.aligned.b32 %0, %1;" :: "r"(tmem), "r"(ncols));
}
__device__ __forceinline__ void tc_commit(uint32_t mbar) {
    asm volatile("tcgen05.commit.cta_group::1.mbarrier::arrive::one.shared::cluster.b64 [%0];"
                 :: "r"(mbar) : "memory");
}
__device__ __forceinline__ void tc_fence_after() {
    asm volatile("tcgen05.fence::after_thread_sync;" ::: "memory");
}
__device__ __forceinline__ void tc_fence_before() {
    asm volatile("tcgen05.fence::before_thread_sync;" ::: "memory");
}
__device__ __forceinline__ void tc_wait_ld() {
    asm volatile("tcgen05.wait::ld.sync.aligned;" ::: "memory");
}
__device__ __forceinline__ void mma_tf32_ss(uint32_t d, uint64_t a, uint64_t b,
                                            uint32_t idesc, uint32_t en) {
    asm volatile("{\n\t.reg .pred p;\n\tsetp.ne.u32 p, %5, 0;\n\t"
                 "tcgen05.mma.cta_group::1.kind::tf32 [%0], %1, %2, %3, {%4,%4,%4,%4}, p;\n\t}"
                 :: "r"(d), "l"(a), "l"(b), "r"(idesc), "r"(0u), "r"(en) : "memory");
}
__device__ __forceinline__ void ldtm_x32(uint32_t* r, uint32_t tmem) {
    asm volatile(
        "tcgen05.ld.sync.aligned.32x32b.x32.b32 "
        "{%0, %1, %2, %3, %4, %5, %6, %7, "
        " %8, %9, %10, %11, %12, %13, %14, %15, "
        " %16, %17, %18, %19, %20, %21, %22, %23, "
        " %24, %25, %26, %27, %28, %29, %30, %31}, [%32];"
        : "=r"(r[0]), "=r"(r[1]), "=r"(r[2]), "=r"(r[3]),
          "=r"(r[4]), "=r"(r[5]), "=r"(r[6]), "=r"(r[7]),
          "=r"(r[8]), "=r"(r[9]), "=r"(r[10]), "=r"(r[11]),
          "=r"(r[12]), "=r"(r[13]), "=r"(r[14]), "=r"(r[15]),
          "=r"(r[16]), "=r"(r[17]), "=r"(r[18]), "=r"(r[19]),
          "=r"(r[20]), "=r"(r[21]), "=r"(r[22]), "=r"(r[23]),
          "=r"(r[24]), "=r"(r[25]), "=r"(r[26]), "=r"(r[27]),
          "=r"(r[28]), "=r"(r[29]), "=r"(r[30]), "=r"(r[31])
        : "r"(tmem));
}
// SMEM descriptor: SW128, version=1, SBO=64 (1024B per 8-row group), LBO=1 (16B)
#define DESC_BASE ((uint64_t(2) << 61) | (uint64_t(1) << 46) | (uint64_t(64) << 32) | (uint64_t(1) << 16))
__device__ __forceinline__ uint64_t make_desc(uint32_t addr) {
    return DESC_BASE | ((uint64_t)(addr >> 4) & 0x3FFF);
}
#endif // HAS_TCGEN05

// ---------------- tile config ----------------
#define TM 128
#define TN 256
#define KC 32                 // K per smem chunk (32 tf32 = 128B rows)
#define NCHUNK (DD / KC)      // 8
// idesc: dtype=F32(1)@4, atype=TF32(2)@7, btype=TF32(2)@10, N/8@17, M/16@24
// (scheme validated: f16 variant reproduces example idesc 0x8080490)
#define IDESC ((1u << 4) | (2u << 7) | (2u << 10) | ((TN / 8) << 17) | ((TM / 16) << 24))

// smem layout (bytes), 1024-aligned tile bases
#define SM_TMEM  0
#define SM_MBAR  8
#define SM_A0    1024
#define SM_A1    (SM_A0 + TM * KC * 4)
#define SM_B0    (SM_A1 + TM * KC * 4)
#define SM_B1    (SM_B0 + TN * KC * 4)
#define SM_TOTAL (SM_B1 + TN * KC * 4)    // 99328

// ---------------------------------------------------------------- zero
__global__ void k_zero() {
    int i = blockIdx.x * blockDim.x + threadIdx.x;
    if (i < BQ) { g_rowsum[i] = 0.f; g_colsum[i] = 0.f; }
}

// ---------------------------------------------------------------- offsets scan (1 block, 1024 thr)
__global__ void k_scan(const int* __restrict__ counts) {
    __shared__ int s[1024];
    int t = threadIdx.x;
    int c0 = counts[4*t+0], c1 = counts[4*t+1], c2 = counts[4*t+2], c3 = counts[4*t+3];
    int tot = c0 + c1 + c2 + c3;
    s[t] = tot;
    __syncthreads();
    for (int off = 1; off < 1024; off <<= 1) {
        int v = (t >= off) ? s[t - off] : 0;
        __syncthreads();
        s[t] += v;
        __syncthreads();
    }
    int excl = s[t] - tot;
    g_offsets[4*t+0] = excl;
    g_offsets[4*t+1] = excl + c0;
    g_offsets[4*t+2] = excl + c0 + c1;
    g_offsets[4*t+3] = excl + c0 + c1 + c2;
}

// ---------------------------------------------------------------- negatives + diagonal
__global__ void k_neg(const float* __restrict__ q, const float* __restrict__ p,
                      const float* __restrict__ n, const int* __restrict__ counts,
                      const float* __restrict__ log_tau) {
    int i = blockIdx.x;
    float inv_tau = get_inv_tau(log_tau);
    __shared__ float qs[DD];
    __shared__ float warp_part[4];
    int tid = threadIdx.x;
    ((float2*)qs)[tid] = ((const float2*)(q + (size_t)i * DD))[tid];
    __syncthreads();
    int w = tid >> 5, lane = tid & 31;
    int cnt = counts[i];
    int off = g_offsets[i];

    float4 b0 = ((const float4*)qs)[lane * 2 + 0];
    float4 b1 = ((const float4*)qs)[lane * 2 + 1];

    float part = 0.f;
    for (int k = w; k < cnt; k += 4) {
        const float* nr = n + (size_t)(off + k) * DD;
        float4 a0 = ((const float4*)nr)[lane * 2 + 0];
        float4 a1 = ((const float4*)nr)[lane * 2 + 1];
        float dot = a0.x*b0.x + a0.y*b0.y + a0.z*b0.z + a0.w*b0.w
                  + a1.x*b1.x + a1.y*b1.y + a1.z*b1.z + a1.w*b1.w;
        #pragma unroll
        for (int m = 16; m > 0; m >>= 1) dot += __shfl_xor_sync(0xFFFFFFFFu, dot, m);
        if (lane == 0) part += __expf(dot * inv_tau);
    }
    if (lane == 0) warp_part[w] = part;

    if (w == 0) {
        const float* pr = p + (size_t)i * DD;
        float4 a0 = ((const float4*)pr)[lane * 2 + 0];
        float4 a1 = ((const float4*)pr)[lane * 2 + 1];
        float dot = a0.x*b0.x + a0.y*b0.y + a0.z*b0.z + a0.w*b0.w
                  + a1.x*b1.x + a1.y*b1.y + a1.z*b1.z + a1.w*b1.w;
        #pragma unroll
        for (int m = 16; m > 0; m >>= 1) dot += __shfl_xor_sync(0xFFFFFFFFu, dot, m);
        if (lane == 0) g_diag[i] = dot * inv_tau;
    }
    __syncthreads();
    if (tid == 0)
        g_negsum[i] = warp_part[0] + warp_part[1] + warp_part[2] + warp_part[3];
}

// ---------------------------------------------------------------- GEMM + exp-sum epilogue
// sm_103a: tcgen05 tf32, 128x256 tile. Other targets: FFMA fallback (two 128x128 halves).
__global__ __launch_bounds__(256, 2)
void k_gemm_tc(const float* __restrict__ q, const float* __restrict__ p,
               const float* __restrict__ log_tau) {
    extern __shared__ char smem[];
#if HAS_TCGEN05
    uint32_t sb = smem_u32(smem);
    int tid = threadIdx.x;
    int wid = tid >> 5, lane = tid & 31;
    int m0 = blockIdx.y * TM;
    int n0 = blockIdx.x * TN;

    if (wid == 0) { tc_alloc(sb + SM_TMEM, 256); tc_relinquish(); }
    if (tid == 0) { mbar_init(sb + SM_MBAR, 1); mbar_init(sb + SM_MBAR + 8, 1); }
    __syncthreads();
    uint32_t tmem;
    asm volatile("ld.shared.b32 %0, [%1];" : "=r"(tmem) : "r"(sb + SM_TMEM));

    // ---- tile loaders (SW128 swizzled K-major, 128B rows) ----
    auto load_a = [&](int k0, char* dst) {
        #pragma unroll
        for (int l = 0; l < (TM * KC / 4) / 256; l++) {
            int id = tid + 256 * l;
            int r = id >> 3, c4 = id & 7;
            float4 v = *(const float4*)(q + (size_t)(m0 + r) * DD + k0 + c4 * 4);
            uint32_t off = (uint32_t)(r * 128 + c4 * 16);
            off ^= ((off >> 3) & 0x70);
            *(float4*)(dst + off) = v;
        }
    };
    auto load_b = [&](int k0, char* dst) {
        #pragma unroll
        for (int l = 0; l < (TN * KC / 4) / 256; l++) {
            int id = tid + 256 * l;
            int r = id >> 3, c4 = id & 7;
            float4 v = *(const float4*)(p + (size_t)(n0 + r) * DD + k0 + c4 * 4);
            uint32_t off = (uint32_t)(r * 128 + c4 * 16);
            off ^= ((off >> 3) & 0x70);
            *(float4*)(dst + off) = v;
        }
    };

    // prologue: chunk 0 into buffer 0
    load_a(0, smem + SM_A0);
    load_b(0, smem + SM_B0);
    __syncthreads();

    int ph0 = 0, ph1 = 0;
    for (int c = 0; c < NCHUNK; c++) {
        int b = c & 1;
        if (tid == 0) {
            fence_async_shared();
            uint64_t ad = make_desc(sb + (b ? SM_A1 : SM_A0));
            uint64_t bd = make_desc(sb + (b ? SM_B1 : SM_B0));
            #pragma unroll
            for (int s = 0; s < 4; s++)     // K=8 tf32 per dispatch, +32B desc step
                mma_tf32_ss(tmem, ad + 2 * s, bd + 2 * s, IDESC, (c > 0) || (s > 0));
            tc_commit(sb + SM_MBAR + 8 * b);
        }
        if (c + 1 < NCHUNK) {
            int nb = (c + 1) & 1;
            if (c >= 1) {
                // buffer nb was consumed by chunk c-1's MMAs (committed to mbar[nb])
                if (nb == 0) { mbar_wait(sb + SM_MBAR, ph0); ph0 ^= 1; }
                else         { mbar_wait(sb + SM_MBAR + 8, ph1); ph1 ^= 1; }
            }
            int k0 = (c + 1) * KC;
            load_a(k0, smem + (nb ? SM_A1 : SM_A0));
            load_b(k0, smem + (nb ? SM_B1 : SM_B0));
        }
        __syncthreads();
    }
    mbar_wait(sb + SM_MBAR + 8, ph1);   // chunk 7 -> mbar1, parity ph1
    tc_fence_after();

    // ---- epilogue: exp + row/col reductions straight out of TMEM ----
    float inv_tau = get_inv_tau(log_tau);
    if (tid < 128) {
        float rowacc = 0.f;
        #pragma unroll
        for (int cc = 0; cc < TN / 32; cc++) {
            uint32_t r[32];
            ldtm_x32(r, tmem + cc * 32);
            tc_wait_ld();
            float v[32];
            #pragma unroll
            for (int j = 0; j < 32; j++)
                v[j] = __expf(__uint_as_float(r[j]) * inv_tau);
            #pragma unroll
            for (int j = 0; j < 32; j++) rowacc += v[j];
            #pragma unroll
            for (int j = 0; j < 32; j++) {
                v[j] += __shfl_xor_sync(0xFFFFFFFFu, v[j], 16);
                v[j] += __shfl_xor_sync(0xFFFFFFFFu, v[j], 8);
                v[j] += __shfl_xor_sync(0xFFFFFFFFu, v[j], 4);
                v[j] += __shfl_xor_sync(0xFFFFFFFFu, v[j], 2);
                v[j] += __shfl_xor_sync(0xFFFFFFFFu, v[j], 1);
                if (lane == j) atomicAdd(&g_colsum[n0 + cc * 32 + j], v[j]);
            }
        }
        atomicAdd(&g_rowsum[m0 + tid], rowacc);
    }
    tc_fence_before();
    __syncthreads();
    if (wid == 0) tc_dealloc(tmem, 256);

#else  // ------------- FFMA fallback (non-sm_103a passes) -------------
    const int BK = 16, SP = 4;
    float* As = (float*)smem;                        // [BK][128+SP]
    float* Bs = As + BK * (128 + SP);                // [BK][128+SP]
    int tid = threadIdx.x;
    int tx = tid & 15, ty = tid >> 4;
    int m0 = blockIdx.y * TM;
    float inv_tau = get_inv_tau(log_tau);

    for (int h = 0; h < 2; h++) {
        int n0 = blockIdx.x * TN + h * 128;
        float acc[8][8];
        #pragma unroll
        for (int r = 0; r < 8; r++)
            #pragma unroll
            for (int c = 0; c < 8; c++) acc[r][c] = 0.f;

        for (int kt = 0; kt < DD / BK; kt++) {
            int k0 = kt * BK;
            #pragma unroll
            for (int l = 0; l < 2; l++) {
                int id = tid + 256 * l;
                int r = id >> 2, c = (id & 3) << 2;
                float4 av = *(const float4*)(q + (size_t)(m0 + r) * DD + k0 + c);
                As[(c+0)*(128+SP)+r] = av.x; As[(c+1)*(128+SP)+r] = av.y;
                As[(c+2)*(128+SP)+r] = av.z; As[(c+3)*(128+SP)+r] = av.w;
                float4 bv = *(const float4*)(p + (size_t)(n0 + r) * DD + k0 + c);
                Bs[(c+0)*(128+SP)+r] = bv.x; Bs[(c+1)*(128+SP)+r] = bv.y;
                Bs[(c+2)*(128+SP)+r] = bv.z; Bs[(c+3)*(128+SP)+r] = bv.w;
            }
            __syncthreads();
            #pragma unroll
            for (int kk = 0; kk < BK; kk++) {
                float ar[8], br[8];
                #pragma unroll
                for (int r = 0; r < 8; r++) ar[r] = As[kk*(128+SP) + ty*8 + r];
                #pragma unroll
                for (int c = 0; c < 8; c++) br[c] = Bs[kk*(128+SP) + tx*8 + c];
                #pragma unroll
                for (int r = 0; r < 8; r++)
                    #pragma unroll
                    for (int c = 0; c < 8; c++)
                        acc[r][c] = fmaf(ar[r], br[c], acc[r][c]);
            }
            __syncthreads();
        }

        #pragma unroll
        for (int r = 0; r < 8; r++)
            #pragma unroll
            for (int c = 0; c < 8; c++)
                acc[r][c] = __expf(acc[r][c] * inv_tau);

        #pragma unroll
        for (int r = 0; r < 8; r++) {
            float v = 0.f;
            #pragma unroll
            for (int c = 0; c < 8; c++) v += acc[r][c];
            v += __shfl_xor_sync(0xFFFFFFFFu, v, 1);
            v += __shfl_xor_sync(0xFFFFFFFFu, v, 2);
            v += __shfl_xor_sync(0xFFFFFFFFu, v, 4);
            v += __shfl_xor_sync(0xFFFFFFFFu, v, 8);
            if (tx == 0) atomicAdd(&g_rowsum[m0 + ty * 8 + r], v);
        }

        float* cb = As;   // 16 x 128 staging
        #pragma unroll
        for (int c = 0; c < 8; c++) {
            float v = 0.f;
            #pragma unroll
            for (int r = 0; r < 8; r++) v += acc[r][c];
            cb[ty * 128 + tx * 8 + c] = v;
        }
        __syncthreads();
        if (tid < 128) {
            float v = 0.f;
            #pragma unroll
            for (int t = 0; t < 16; t++) v += cb[t * 128 + tid];
            atomicAdd(&g_colsum[n0 + tid], v);
        }
        __syncthreads();
    }
#endif
}

// ---------------------------------------------------------------- finalize (1 block)
__global__ void k_final(float* __restrict__ out) {
    __shared__ float red[256];
    int tid = threadIdx.x;
    float a = 0.f;
    for (int i = tid; i < BQ; i += 256) {
        a += 2.f * g_diag[i]
           - logf(g_rowsum[i] + g_negsum[i])
           - logf(g_colsum[i]);
    }
    red[tid] = a;
    __syncthreads();
    for (int s = 128; s > 0; s >>= 1) {
        if (tid < s) red[tid] += red[tid + s];
        __syncthreads();
    }
    if (tid == 0) out[0] = -red[0] / (2.f * (float)BQ);
}

// ---------------------------------------------------------------- launch
extern "C" void kernel_launch(void* const* d_in, const int* in_sizes, int n_in,
                              void* d_out, int out_size) {
    const float* q       = (const float*)d_in[0];
    const float* p       = (const float*)d_in[1];
    const float* n       = (const float*)d_in[2];
    const int*   counts  = (const int*)d_in[3];
    const float* log_tau = (const float*)d_in[4];
    float* out = (float*)d_out;

    static bool attr_set = false;
    if (!attr_set) {
        cudaFuncSetAttribute(k_gemm_tc, cudaFuncAttributeMaxDynamicSharedMemorySize, SM_TOTAL);
        attr_set = true;
    }

    k_zero<<<(BQ + 255) / 256, 256>>>();
    k_scan<<<1, 1024>>>(counts);
    k_neg<<<BQ, 128>>>(q, p, n, counts, log_tau);
    dim3 grid(BQ / TN, BQ / TM);
    k_gemm_tc<<<grid, 256, SM_TOTAL>>>(q, p, log_tau);
    k_final<<<1, 256>>>(out);
}

// round 5
// speedup vs baseline: 2.2011x; 1.0486x over previous
#include <cuda_runtime.h>
#include <math.h>
#include <stdint.h>

#define BQ 4096
#define DD 256
#define NNEG 32768

// ---------------- arch-feature guard: tcgen05 only exists on sm_103a/sm_100a ----------------
#if (defined(__CUDA_ARCH_FEAT_SM103_ALL) || defined(__CUDA_ARCH_FEAT_SM100_ALL) || \
     (defined(__CUDA_ARCH_SPECIFIC__) && (__CUDA_ARCH_SPECIFIC__ == 1030 || __CUDA_ARCH_SPECIFIC__ == 1000)) || \
     (defined(__CUDA_ARCH_FAMILY_SPECIFIC__) && (__CUDA_ARCH_FAMILY_SPECIFIC__ == 1030 || __CUDA_ARCH_FAMILY_SPECIFIC__ == 1000)))
#define HAS_TCGEN05 1
#else
#define HAS_TCGEN05 0
#endif

// ---------------- scratch (no allocations allowed) ----------------
__device__ float g_rowsum[BQ];
__device__ float g_colsum[BQ];
__device__ float g_negsum[BQ];
__device__ float g_diag[BQ];
__device__ int   g_offsets[BQ];

__device__ __forceinline__ float get_inv_tau(const float* log_tau) {
    float t = expf(log_tau[0]);
    t = fminf(fmaxf(t, 1e-4f), 1.0f);
    return 1.0f / t;
}

// ---------------- generic PTX helpers (sm_80+; no guard needed) ----------------
__device__ __forceinline__ uint32_t smem_u32(const void* p) {
    return (uint32_t)__cvta_generic_to_shared(p);
}
__device__ __forceinline__ void mbar_init(uint32_t a, uint32_t cnt) {
    asm volatile("mbarrier.init.shared.b64 [%0], %1;" :: "r"(a), "r"(cnt) : "memory");
}
__device__ __forceinline__ void mbar_wait(uint32_t a, uint32_t phase) {
    uint32_t done;
    do {
        asm volatile("{\n\t.reg .pred p;\n\t"
                     "mbarrier.try_wait.parity.shared::cta.b64 p, [%1], %2, 0x989680;\n\t"
                     "selp.b32 %0, 1, 0, p;\n\t}"
                     : "=r"(done) : "r"(a), "r"(phase) : "memory");
    } while (!done);
}
__device__ __forceinline__ void cp_async16(uint32_t dst, const void* src) {
    asm volatile("cp.async.cg.shared.global [%0], [%1], 16;"
                 :: "r"(dst), "l"(src) : "memory");
}
// NOTE: .noinc is load-bearing. Without it the arrive first INCREMENTS the
// pending count, making it net-neutral vs the expected 256 -> deadlock (R4).
__device__ __forceinline__ void cp_async_arrive_noinc(uint32_t mbar) {
    asm volatile("cp.async.mbarrier.arrive.noinc.shared::cta.b64 [%0];" :: "r"(mbar) : "memory");
}
__device__ __forceinline__ void fence_async_shared() {
    asm volatile("fence.proxy.async.shared::cta;" ::: "memory");
}

#if HAS_TCGEN05
// ---------------- tcgen05 helpers (sm_103a only) ----------------
__device__ __forceinline__ void tc_alloc(uint32_t smem_dst, uint32_t ncols) {
    asm volatile("tcgen05.alloc.cta_group::1.sync.aligned.shared::cta.b32 [%0], %1;"
                 :: "r"(smem_dst), "r"(ncols) : "memory");
}
__device__ __forceinline__ void tc_relinquish() {
    asm volatile("tcgen05.relinquish_alloc_permit.cta_group::1.sync.aligned;");
}
__device__ __forceinline__ void tc_dealloc(uint32_t tmem, uint32_t ncols) {
    asm volatile("tcgen05.dealloc.cta_group::1.sync.aligned.b32 %0, %1;" :: "r"(tmem), "r"(ncols));
}
__device__ __forceinline__ void tc_commit(uint32_t mbar) {
    asm volatile("tcgen05.commit.cta_group::1.mbarrier::arrive::one.shared::cluster.b64 [%0];"
                 :: "r"(mbar) : "memory");
}
__device__ __forceinline__ void tc_fence_after() {
    asm volatile("tcgen05.fence::after_thread_sync;" ::: "memory");
}
__device__ __forceinline__ void tc_fence_before() {
    asm volatile("tcgen05.fence::before_thread_sync;" ::: "memory");
}
__device__ __forceinline__ void tc_wait_ld() {
    asm volatile("tcgen05.wait::ld.sync.aligned;" ::: "memory");
}
__device__ __forceinline__ void mma_tf32_ss(uint32_t d, uint64_t a, uint64_t b,
                                            uint32_t idesc, uint32_t en) {
    asm volatile("{\n\t.reg .pred p;\n\tsetp.ne.u32 p, %5, 0;\n\t"
                 "tcgen05.mma.cta_group::1.kind::tf32 [%0], %1, %2, %3, {%4,%4,%4,%4}, p;\n\t}"
                 :: "r"(d), "l"(a), "l"(b), "r"(idesc), "r"(0u), "r"(en) : "memory");
}
__device__ __forceinline__ void ldtm_x32(uint32_t* r, uint32_t tmem) {
    asm volatile(
        "tcgen05.ld.sync.aligned.32x32b.x32.b32 "
        "{%0, %1, %2, %3, %4, %5, %6, %7, "
        " %8, %9, %10, %11, %12, %13, %14, %15, "
        " %16, %17, %18, %19, %20, %21, %22, %23, "
        " %24, %25, %26, %27, %28, %29, %30, %31}, [%32];"
        : "=r"(r[0]), "=r"(r[1]), "=r"(r[2]), "=r"(r[3]),
          "=r"(r[4]), "=r"(r[5]), "=r"(r[6]), "=r"(r[7]),
          "=r"(r[8]), "=r"(r[9]), "=r"(r[10]), "=r"(r[11]),
          "=r"(r[12]), "=r"(r[13]), "=r"(r[14]), "=r"(r[15]),
          "=r"(r[16]), "=r"(r[17]), "=r"(r[18]), "=r"(r[19]),
          "=r"(r[20]), "=r"(r[21]), "=r"(r[22]), "=r"(r[23]),
          "=r"(r[24]), "=r"(r[25]), "=r"(r[26]), "=r"(r[27]),
          "=r"(r[28]), "=r"(r[29]), "=r"(r[30]), "=r"(r[31])
        : "r"(tmem));
}
// SMEM descriptor: SW128, version=1, SBO=64 (1024B per 8-row group), LBO=1 (16B)
#define DESC_BASE ((uint64_t(2) << 61) | (uint64_t(1) << 46) | (uint64_t(64) << 32) | (uint64_t(1) << 16))
__device__ __forceinline__ uint64_t make_desc(uint32_t addr) {
    return DESC_BASE | ((uint64_t)(addr >> 4) & 0x3FFF);
}
#endif // HAS_TCGEN05

// ---------------- tile config ----------------
#define TM 128
#define TN 256
#define KC 32                 // K per smem chunk (32 tf32 = 128B rows)
#define NCHUNK (DD / KC)      // 8
// idesc: dtype=F32(1)@4, atype=TF32(2)@7, btype=TF32(2)@10, N/8@17, M/16@24
#define IDESC ((1u << 4) | (2u << 7) | (2u << 10) | ((TN / 8) << 17) | ((TM / 16) << 24))

// smem layout (bytes)
#define SM_TMEM  0
#define SM_MBAR  64           // full0, full1, empty0, empty1, done (8B each)
#define SM_A0    1024
#define SM_A1    (SM_A0 + TM * KC * 4)
#define SM_B0    (SM_A1 + TM * KC * 4)
#define SM_B1    (SM_B0 + TN * KC * 4)
#define SM_TOTAL (SM_B1 + TN * KC * 4)    // 99328

// ---------------------------------------------------------------- zero
__global__ void k_zero() {
    int i = blockIdx.x * blockDim.x + threadIdx.x;
    if (i < BQ) { g_rowsum[i] = 0.f; g_colsum[i] = 0.f; }
}

// ---------------------------------------------------------------- offsets scan (1 block, 1024 thr)
__global__ void k_scan(const int* __restrict__ counts) {
    __shared__ int s[1024];
    int t = threadIdx.x;
    int c0 = counts[4*t+0], c1 = counts[4*t+1], c2 = counts[4*t+2], c3 = counts[4*t+3];
    int tot = c0 + c1 + c2 + c3;
    s[t] = tot;
    __syncthreads();
    for (int off = 1; off < 1024; off <<= 1) {
        int v = (t >= off) ? s[t - off] : 0;
        __syncthreads();
        s[t] += v;
        __syncthreads();
    }
    int excl = s[t] - tot;
    g_offsets[4*t+0] = excl;
    g_offsets[4*t+1] = excl + c0;
    g_offsets[4*t+2] = excl + c0 + c1;
    g_offsets[4*t+3] = excl + c0 + c1 + c2;
}

// ---------------------------------------------------------------- negatives + diagonal
__global__ void k_neg(const float* __restrict__ q, const float* __restrict__ p,
                      const float* __restrict__ n, const int* __restrict__ counts,
                      const float* __restrict__ log_tau) {
    int i = blockIdx.x;
    float inv_tau = get_inv_tau(log_tau);
    __shared__ float qs[DD];
    __shared__ float warp_part[4];
    int tid = threadIdx.x;
    ((float2*)qs)[tid] = ((const float2*)(q + (size_t)i * DD))[tid];
    __syncthreads();
    int w = tid >> 5, lane = tid & 31;
    int cnt = counts[i];
    int off = g_offsets[i];

    float4 b0 = ((const float4*)qs)[lane * 2 + 0];
    float4 b1 = ((const float4*)qs)[lane * 2 + 1];

    float part = 0.f;
    for (int k = w; k < cnt; k += 4) {
        const float* nr = n + (size_t)(off + k) * DD;
        float4 a0 = ((const float4*)nr)[lane * 2 + 0];
        float4 a1 = ((const float4*)nr)[lane * 2 + 1];
        float dot = a0.x*b0.x + a0.y*b0.y + a0.z*b0.z + a0.w*b0.w
                  + a1.x*b1.x + a1.y*b1.y + a1.z*b1.z + a1.w*b1.w;
        #pragma unroll
        for (int m = 16; m > 0; m >>= 1) dot += __shfl_xor_sync(0xFFFFFFFFu, dot, m);
        if (lane == 0) part += __expf(dot * inv_tau);
    }
    if (lane == 0) warp_part[w] = part;

    if (w == 0) {
        const float* pr = p + (size_t)i * DD;
        float4 a0 = ((const float4*)pr)[lane * 2 + 0];
        float4 a1 = ((const float4*)pr)[lane * 2 + 1];
        float dot = a0.x*b0.x + a0.y*b0.y + a0.z*b0.z + a0.w*b0.w
                  + a1.x*b1.x + a1.y*b1.y + a1.z*b1.z + a1.w*b1.w;
        #pragma unroll
        for (int m = 16; m > 0; m >>= 1) dot += __shfl_xor_sync(0xFFFFFFFFu, dot, m);
        if (lane == 0) g_diag[i] = dot * inv_tau;
    }
    __syncthreads();
    if (tid == 0)
        g_negsum[i] = warp_part[0] + warp_part[1] + warp_part[2] + warp_part[3];
}

// ---------------------------------------------------------------- GEMM + exp-sum epilogue
// sm_103a: tcgen05 tf32, cp.async mbarrier pipeline, no __syncthreads in mainloop.
__global__ __launch_bounds__(256, 2)
void k_gemm_tc(const float* __restrict__ q, const float* __restrict__ p,
               const float* __restrict__ log_tau) {
    extern __shared__ char smem[];
#if HAS_TCGEN05
    uint32_t sb = smem_u32(smem);
    int tid = threadIdx.x;
    int wid = tid >> 5, lane = tid & 31;
    int m0 = blockIdx.y * TM;
    int n0 = blockIdx.x * TN;

    uint32_t mb_full0  = sb + SM_MBAR + 0;
    uint32_t mb_full1  = sb + SM_MBAR + 8;
    uint32_t mb_empty0 = sb + SM_MBAR + 16;
    uint32_t mb_empty1 = sb + SM_MBAR + 24;
    uint32_t mb_done   = sb + SM_MBAR + 32;

    if (wid == 0) { tc_alloc(sb + SM_TMEM, 256); tc_relinquish(); }
    if (tid == 0) {
        mbar_init(mb_full0, 256); mbar_init(mb_full1, 256);
        mbar_init(mb_empty0, 1);  mbar_init(mb_empty1, 1);
        mbar_init(mb_done, 1);
    }
    __syncthreads();
    uint32_t tmem;
    asm volatile("ld.shared.b32 %0, [%1];" : "=r"(tmem) : "r"(sb + SM_TMEM));

    // per-thread precomputed load geometry: each thread moves 12 x 16B per chunk
    uint32_t a_soff[4], b_soff[8];
    const float* a_gptr[4];
    const float* b_gptr[8];
    #pragma unroll
    for (int l = 0; l < 4; l++) {
        int id = tid + 256 * l;
        int r = id >> 3, c4 = id & 7;
        uint32_t off = (uint32_t)(r * 128 + c4 * 16);
        a_soff[l] = off ^ ((off >> 3) & 0x70);
        a_gptr[l] = q + (size_t)(m0 + r) * DD + c4 * 4;
    }
    #pragma unroll
    for (int l = 0; l < 8; l++) {
        int id = tid + 256 * l;
        int r = id >> 3, c4 = id & 7;
        uint32_t off = (uint32_t)(r * 128 + c4 * 16);
        b_soff[l] = off ^ ((off >> 3) & 0x70);
        b_gptr[l] = p + (size_t)(n0 + r) * DD + c4 * 4;
    }

    int phF0 = 0, phF1 = 0, phE0 = 0, phE1 = 0;
    #pragma unroll 1
    for (int c = 0; c < NCHUNK; c++) {
        int b = c & 1;
        uint32_t abase = sb + (b ? SM_A1 : SM_A0);
        uint32_t bbase = sb + (b ? SM_B1 : SM_B0);
        uint32_t full  = b ? mb_full1 : mb_full0;
        uint32_t empty = b ? mb_empty1 : mb_empty0;

        if (c >= 2) {
            if (b == 0) { mbar_wait(mb_empty0, phE0); phE0 ^= 1; }
            else        { mbar_wait(mb_empty1, phE1); phE1 ^= 1; }
        }
        int k0 = c * KC;
        #pragma unroll
        for (int l = 0; l < 4; l++) cp_async16(abase + a_soff[l], a_gptr[l] + k0);
        #pragma unroll
        for (int l = 0; l < 8; l++) cp_async16(bbase + b_soff[l], b_gptr[l] + k0);
        cp_async_arrive_noinc(full);

        if (tid == 0) {
            if (b == 0) { mbar_wait(mb_full0, phF0); phF0 ^= 1; }
            else        { mbar_wait(mb_full1, phF1); phF1 ^= 1; }
            fence_async_shared();
            uint64_t ad = make_desc(abase);
            uint64_t bd = make_desc(bbase);
            #pragma unroll
            for (int s = 0; s < 4; s++)     // K=8 tf32 per dispatch, +32B desc step
                mma_tf32_ss(tmem, ad + 2 * s, bd + 2 * s, IDESC, (c > 0) || (s > 0));
            tc_commit(empty);
        }
    }
    if (tid == 0) tc_commit(mb_done);
    mbar_wait(mb_done, 0);
    tc_fence_after();

    // ---- epilogue: exp + row/col reductions straight out of TMEM ----
    float inv_tau = get_inv_tau(log_tau);
    if (tid < 128) {
        float rowacc = 0.f;
        #pragma unroll
        for (int cc = 0; cc < TN / 32; cc++) {
            uint32_t r[32];
            ldtm_x32(r, tmem + cc * 32);
            tc_wait_ld();
            float v[32];
            #pragma unroll
            for (int j = 0; j < 32; j++)
                v[j] = __expf(__uint_as_float(r[j]) * inv_tau);
            #pragma unroll
            for (int j = 0; j < 32; j++) rowacc += v[j];
            #pragma unroll
            for (int j = 0; j < 32; j++) {
                v[j] += __shfl_xor_sync(0xFFFFFFFFu, v[j], 16);
                v[j] += __shfl_xor_sync(0xFFFFFFFFu, v[j], 8);
                v[j] += __shfl_xor_sync(0xFFFFFFFFu, v[j], 4);
                v[j] += __shfl_xor_sync(0xFFFFFFFFu, v[j], 2);
                v[j] += __shfl_xor_sync(0xFFFFFFFFu, v[j], 1);
                if (lane == j) atomicAdd(&g_colsum[n0 + cc * 32 + j], v[j]);
            }
        }
        atomicAdd(&g_rowsum[m0 + tid], rowacc);
    }
    tc_fence_before();
    __syncthreads();
    if (wid == 0) tc_dealloc(tmem, 256);

#else  // ------------- FFMA fallback (non-sm_103a passes) -------------
    const int BK = 16, SP = 4;
    float* As = (float*)smem;
    float* Bs = As + BK * (128 + SP);
    int tid = threadIdx.x;
    int tx = tid & 15, ty = tid >> 4;
    int m0 = blockIdx.y * TM;
    float inv_tau = get_inv_tau(log_tau);

    for (int h = 0; h < 2; h++) {
        int n0 = blockIdx.x * TN + h * 128;
        float acc[8][8];
        #pragma unroll
        for (int r = 0; r < 8; r++)
            #pragma unroll
            for (int c = 0; c < 8; c++) acc[r][c] = 0.f;

        for (int kt = 0; kt < DD / BK; kt++) {
            int k0 = kt * BK;
            #pragma unroll
            for (int l = 0; l < 2; l++) {
                int id = tid + 256 * l;
                int r = id >> 2, c = (id & 3) << 2;
                float4 av = *(const float4*)(q + (size_t)(m0 + r) * DD + k0 + c);
                As[(c+0)*(128+SP)+r] = av.x; As[(c+1)*(128+SP)+r] = av.y;
                As[(c+2)*(128+SP)+r] = av.z; As[(c+3)*(128+SP)+r] = av.w;
                float4 bv = *(const float4*)(p + (size_t)(n0 + r) * DD + k0 + c);
                Bs[(c+0)*(128+SP)+r] = bv.x; Bs[(c+1)*(128+SP)+r] = bv.y;
                Bs[(c+2)*(128+SP)+r] = bv.z; Bs[(c+3)*(128+SP)+r] = bv.w;
            }
            __syncthreads();
            #pragma unroll
            for (int kk = 0; kk < BK; kk++) {
                float ar[8], br[8];
                #pragma unroll
                for (int r = 0; r < 8; r++) ar[r] = As[kk*(128+SP) + ty*8 + r];
                #pragma unroll
                for (int c = 0; c < 8; c++) br[c] = Bs[kk*(128+SP) + tx*8 + c];
                #pragma unroll
                for (int r = 0; r < 8; r++)
                    #pragma unroll
                    for (int c = 0; c < 8; c++)
                        acc[r][c] = fmaf(ar[r], br[c], acc[r][c]);
            }
            __syncthreads();
        }

        #pragma unroll
        for (int r = 0; r < 8; r++)
            #pragma unroll
            for (int c = 0; c < 8; c++)
                acc[r][c] = __expf(acc[r][c] * inv_tau);

        #pragma unroll
        for (int r = 0; r < 8; r++) {
            float v = 0.f;
            #pragma unroll
            for (int c = 0; c < 8; c++) v += acc[r][c];
            v += __shfl_xor_sync(0xFFFFFFFFu, v, 1);
            v += __shfl_xor_sync(0xFFFFFFFFu, v, 2);
            v += __shfl_xor_sync(0xFFFFFFFFu, v, 4);
            v += __shfl_xor_sync(0xFFFFFFFFu, v, 8);
            if (tx == 0) atomicAdd(&g_rowsum[m0 + ty * 8 + r], v);
        }

        float* cb = As;
        #pragma unroll
        for (int c = 0; c < 8; c++) {
            float v = 0.f;
            #pragma unroll
            for (int r = 0; r < 8; r++) v += acc[r][c];
            cb[ty * 128 + tx * 8 + c] = v;
        }
        __syncthreads();
        if (tid < 128) {
            float v = 0.f;
            #pragma unroll
            for (int t = 0; t < 16; t++) v += cb[t * 128 + tid];
            atomicAdd(&g_colsum[n0 + tid], v);
        }
        __syncthreads();
    }
#endif
}

// ---------------------------------------------------------------- finalize (1 block)
__global__ void k_final(float* __restrict__ out) {
    __shared__ float red[256];
    int tid = threadIdx.x;
    float a = 0.f;
    for (int i = tid; i < BQ; i += 256) {
        a += 2.f * g_diag[i]
           - logf(g_rowsum[i] + g_negsum[i])
           - logf(g_colsum[i]);
    }
    red[tid] = a;
    __syncthreads();
    for (int s = 128; s > 0; s >>= 1) {
        if (tid < s) red[tid] += red[tid + s];
        __syncthreads();
    }
    if (tid == 0) out[0] = -red[0] / (2.f * (float)BQ);
}

// ---------------------------------------------------------------- launch
extern "C" void kernel_launch(void* const* d_in, const int* in_sizes, int n_in,
                              void* d_out, int out_size) {
    const float* q       = (const float*)d_in[0];
    const float* p       = (const float*)d_in[1];
    const float* n       = (const float*)d_in[2];
    const int*   counts  = (const int*)d_in[3];
    const float* log_tau = (const float*)d_in[4];
    float* out = (float*)d_out;

    static bool attr_set = false;
    if (!attr_set) {
        cudaFuncSetAttribute(k_gemm_tc, cudaFuncAttributeMaxDynamicSharedMemorySize, SM_TOTAL);
        attr_set = true;
    }

    k_zero<<<(BQ + 255) / 256, 256>>>();
    k_scan<<<1, 1024>>>(counts);
    k_neg<<<BQ, 128>>>(q, p, n, counts, log_tau);
    dim3 grid(BQ / TN, BQ / TM);
    k_gemm_tc<<<grid, 256, SM_TOTAL>>>(q, p, log_tau);
    k_final<<<1, 256>>>(out);
}